// round 1
// baseline (speedup 1.0000x reference)
#include <cuda_runtime.h>

// Problem constants (fixed by the dataset)
#define HH 50
#define GG 200          // 4*H
#define TT 2048
#define BB 8192
#define BPB 64          // batches per block
#define PAIRS 32        // batch pairs per block (float2-packed)
#define NW 8            // warps per block
#define GPW 25          // gates per warp

typedef unsigned long long ull;

// ---- packed f32x2 helpers (Blackwell-only: ptxas will NOT auto-fuse) ----
__device__ __forceinline__ ull pack2(float lo, float hi) {
    ull r; asm("mov.b64 %0, {%1, %2};" : "=l"(r) : "f"(lo), "f"(hi)); return r;
}
__device__ __forceinline__ void unpack2(ull v, float &lo, float &hi) {
    asm("mov.b64 {%0, %1}, %2;" : "=f"(lo), "=f"(hi) : "l"(v));
}
__device__ __forceinline__ ull ffma2(ull a, ull b, ull c) {
    ull d; asm("fma.rn.f32x2 %0, %1, %2, %3;" : "=l"(d) : "l"(a), "l"(b), "l"(c)); return d;
}
__device__ __forceinline__ ull fadd2(ull a, ull b) {
    ull d; asm("add.rn.f32x2 %0, %1, %2;" : "=l"(d) : "l"(a), "l"(b)); return d;
}

// accurate-enough activations (EX2 ~2ulp, RCP-based div ~1ulp), overflow-safe
__device__ __forceinline__ float sigm(float x) {
    return __fdividef(1.0f, 1.0f + __expf(-x));
}
__device__ __forceinline__ float tanh_r(float x) {
    float a = fabsf(x);
    float e = __expf(2.0f * a);              // inf for large a -> 2/inf = 0 -> +-1, graceful
    float r = 1.0f - __fdividef(2.0f, e + 1.0f);
    return copysignf(r, x);
}

// Dynamic shared layout
//   wdup : ull[GG*HH]      80000 B   (W_hh duplicated (w,w) per entry)
//   hsh  : ull[HH*PAIRS]   12800 B   h state, [j][pair]
//   zsh  : ull[GG*PAIRS]   51200 B   gate pre-activations, [g][pair]
//   wih_s: float[GG]         800 B
//   bs_s : float[GG]         800 B   (b_ih + b_hh)
//   wlin : float[HH]         200 B
#define OFF_WDUP 0
#define OFF_HSH  80000
#define OFF_ZSH  92800
#define OFF_WIH  144000
#define OFF_BS   144800
#define OFF_WLIN 145600
#define SMEM_BYTES 145824

__global__ __launch_bounds__(256, 1)
void lstm_persist_kernel(const float* __restrict__ x,
                         const float* __restrict__ W_ih,
                         const float* __restrict__ W_hh,
                         const float* __restrict__ b_ih,
                         const float* __restrict__ b_hh,
                         const float* __restrict__ W_lin,
                         const float* __restrict__ b_lin,
                         float* __restrict__ out)
{
    extern __shared__ char smem[];
    ull*   wdup  = (ull*)(smem + OFF_WDUP);
    ull*   hsh   = (ull*)(smem + OFF_HSH);
    ull*   zsh   = (ull*)(smem + OFF_ZSH);
    float* wih_s = (float*)(smem + OFF_WIH);
    float* bs_s  = (float*)(smem + OFF_BS);
    float* wlin  = (float*)(smem + OFF_WLIN);

    const int tid = threadIdx.x;
    const int w   = tid >> 5;     // role warp: gates [25w, 25w+25)
    const int l   = tid & 31;     // batch pair within block

    // ---- init shared ----
    for (int i = tid; i < GG * HH; i += 256) {
        float v = W_hh[i];
        wdup[i] = pack2(v, v);
    }
    for (int i = tid; i < GG; i += 256) {
        wih_s[i] = W_ih[i];
        bs_s[i]  = b_ih[i] + b_hh[i];
    }
    for (int i = tid; i < HH; i += 256) wlin[i] = W_lin[i];
    for (int i = tid; i < HH * PAIRS; i += 256) hsh[i] = 0ull;
    __syncthreads();

    // batches for this thread's pair
    const int b0 = blockIdx.x * BPB + 2 * l;
    const float* __restrict__ xp0 = x + (size_t)b0 * TT;
    const float* __restrict__ xp1 = xp0 + TT;

    // phase-2 ownership: warps 0,1 own 7 elements; warps 2..7 own 6
    const int js = w * 6 + min(w, 2);
    const int jc = 6 + (w < 2 ? 1 : 0);
    float cl[7], ch[7];
#pragma unroll
    for (int k = 0; k < 7; ++k) { cl[k] = 0.0f; ch[k] = 0.0f; }

    const int gbase = w * GPW;

    float xa0 = xp0[0];
    float xa1 = xp1[0];

    for (int t = 0; t < TT; ++t) {
        // prefetch next timestep's x (consumed next iteration)
        const int tn = (t + 1 < TT) ? (t + 1) : (TT - 1);
        const float xn0 = xp0[tn];
        const float xn1 = xp1[tn];

        // ---- phase 1: gate matvec (packed f32x2) ----
        ull h2[HH];
#pragma unroll
        for (int j = 0; j < HH; ++j) h2[j] = hsh[j * PAIRS + l];

#pragma unroll 5
        for (int gg = 0; gg < GPW; ++gg) {
            const int g = gbase + gg;
            const float wih = wih_s[g];
            const float bs  = bs_s[g];
            ull a0 = pack2(fmaf(wih, xa0, bs), fmaf(wih, xa1, bs));
            ull a1 = 0ull, a2 = 0ull, a3 = 0ull;
            const ull* __restrict__ wr = wdup + g * HH;
#pragma unroll
            for (int j = 0; j < 48; j += 4) {
                a0 = ffma2(wr[j],     h2[j],     a0);
                a1 = ffma2(wr[j + 1], h2[j + 1], a1);
                a2 = ffma2(wr[j + 2], h2[j + 2], a2);
                a3 = ffma2(wr[j + 3], h2[j + 3], a3);
            }
            a0 = ffma2(wr[48], h2[48], a0);
            a1 = ffma2(wr[49], h2[49], a1);
            a0 = fadd2(a0, a2);
            a1 = fadd2(a1, a3);
            zsh[g * PAIRS + l] = fadd2(a0, a1);
        }
        __syncthreads();

        // ---- phase 2: activations + state update for owned elements ----
#pragma unroll
        for (int k = 0; k < 7; ++k) {
            if (k < jc) {
                const int j = js + k;
                float zi0, zi1, zf0, zf1, zg0, zg1, zo0, zo1;
                unpack2(zsh[(0 * HH + j) * PAIRS + l], zi0, zi1);
                unpack2(zsh[(1 * HH + j) * PAIRS + l], zf0, zf1);
                unpack2(zsh[(2 * HH + j) * PAIRS + l], zg0, zg1);
                unpack2(zsh[(3 * HH + j) * PAIRS + l], zo0, zo1);

                const float i0 = sigm(zi0), f0 = sigm(zf0);
                const float g0 = tanh_r(zg0), o0 = sigm(zo0);
                const float i1 = sigm(zi1), f1 = sigm(zf1);
                const float g1 = tanh_r(zg1), o1 = sigm(zo1);

                const float c0 = fmaf(f0, cl[k], i0 * g0);
                const float c1 = fmaf(f1, ch[k], i1 * g1);
                cl[k] = c0; ch[k] = c1;

                const float h0 = o0 * tanh_r(c0);
                const float h1 = o1 * tanh_r(c1);
                hsh[j * PAIRS + l] = pack2(h0, h1);
            }
        }
        __syncthreads();

        xa0 = xn0;
        xa1 = xn1;
    }

    // ---- final projection: out[b] = h_last . W_lin + b_lin ----
    if (w == 0) {
        const float bl = b_lin[0];
        float s0 = bl, s1 = bl;
#pragma unroll
        for (int j = 0; j < HH; ++j) {
            float h0, h1;
            unpack2(hsh[j * PAIRS + l], h0, h1);
            const float wl = wlin[j];
            s0 = fmaf(wl, h0, s0);
            s1 = fmaf(wl, h1, s1);
        }
        out[b0]     = s0;
        out[b0 + 1] = s1;
    }
}

extern "C" void kernel_launch(void* const* d_in, const int* in_sizes, int n_in,
                              void* d_out, int out_size)
{
    const float* x     = (const float*)d_in[0];
    const float* W_ih  = (const float*)d_in[1];
    const float* W_hh  = (const float*)d_in[2];
    const float* b_ih  = (const float*)d_in[3];
    const float* b_hh  = (const float*)d_in[4];
    const float* W_lin = (const float*)d_in[5];
    const float* b_lin = (const float*)d_in[6];
    float* out = (float*)d_out;

    cudaFuncSetAttribute(lstm_persist_kernel,
                         cudaFuncAttributeMaxDynamicSharedMemorySize, SMEM_BYTES);

    lstm_persist_kernel<<<BB / BPB, 256, SMEM_BYTES>>>(
        x, W_ih, W_hh, b_ih, b_hh, W_lin, b_lin, out);
}

// round 4
// speedup vs baseline: 1.0420x; 1.0420x over previous
#include <cuda_runtime.h>

// Fixed problem shape
#define HH   50
#define GG   200          // 4*H
#define TT   2048
#define BB   8192
#define BPB  64           // batches per block
#define NW   10           // warps per block
#define NTHR 320
#define JPW  5            // j per warp (10*5 = 50)

typedef unsigned long long ull;

// ---- packed f32x2 helpers (PTX-only; ptxas never auto-fuses) ----
__device__ __forceinline__ ull pack2(float lo, float hi) {
    ull r; asm("mov.b64 %0, {%1, %2};" : "=l"(r) : "f"(lo), "f"(hi)); return r;
}
__device__ __forceinline__ void unpack2(ull v, float &lo, float &hi) {
    asm("mov.b64 {%0, %1}, %2;" : "=f"(lo), "=f"(hi) : "l"(v));
}
__device__ __forceinline__ ull ffma2(ull a, ull b, ull c) {
    ull d; asm("fma.rn.f32x2 %0, %1, %2, %3;" : "=l"(d) : "l"(a), "l"(b), "l"(c)); return d;
}
__device__ __forceinline__ ull fadd2(ull a, ull b) {
    ull d; asm("add.rn.f32x2 %0, %1, %2;" : "=l"(d) : "l"(a), "l"(b)); return d;
}

// accurate activations (EX2 + RCP), overflow-safe
__device__ __forceinline__ float sigm(float x) {
    return __fdividef(1.0f, 1.0f + __expf(-x));
}
__device__ __forceinline__ float tanh_r(float x) {
    float a = fabsf(x);
    float e = __expf(2.0f * a);
    float r = 1.0f - __fdividef(2.0f, e + 1.0f);
    return copysignf(r, x);
}

// ---- shared memory layout (dynamic) ----
// wsh  : float[200][52]  (W_hh rows, j-padded with zeros)        41600 B @ 0
// hsw  : 64 rows x 256 B (h, XOR-swizzled 16B units)             16384 B @ 41728
// xt   : float[64][66]   (x tile, 64 timesteps)                  16896 B @ 58112
// wbsh : float2[200]     (W_ih[g], b_ih[g]+b_hh[g])               1600 B @ 75008
// wlin : float[52]                                                 208 B @ 76608
#define OFF_W    0
#define OFF_H    41728
#define OFF_X    58112
#define OFF_WB   75008
#define OFF_WLIN 76608
#define SMEM_BYTES 76816
#define XROW 66

// swizzled byte offset of 16B-unit k in batch-row b
__device__ __forceinline__ int h_unit_off(int b, int k) {
    return b * 256 + ((k ^ ((b >> 1) & 7)) << 4);
}
// swizzled byte offset of scalar element (b, j)
__device__ __forceinline__ int h_elem_off(int b, int j) {
    return b * 256 + (((j >> 2) ^ ((b >> 1) & 7)) << 4) + (j & 3) * 4;
}

__global__ __launch_bounds__(NTHR, 1)
void lstm_persist_kernel(const float* __restrict__ x,
                         const float* __restrict__ W_ih,
                         const float* __restrict__ W_hh,
                         const float* __restrict__ b_ih,
                         const float* __restrict__ b_hh,
                         const float* __restrict__ W_lin,
                         const float* __restrict__ b_lin,
                         float* __restrict__ out)
{
    extern __shared__ char smem[];
    float* wsh   = (float*)(smem + OFF_W);
    char*  hsw   = smem + OFF_H;
    float* xt    = (float*)(smem + OFF_X);
    float2* wbsh = (float2*)(smem + OFF_WB);
    float* wlin  = (float*)(smem + OFF_WLIN);

    const int tid = threadIdx.x;
    const int w   = tid / 32;       // warp id: owns j in [5w, 5w+5)
    const int l   = tid & 31;       // lane = batch pair

    // ---- init shared ----
    for (int i = tid; i < GG * 52; i += NTHR) {
        int g = i / 52, j = i - g * 52;
        wsh[i] = (j < HH) ? W_hh[g * HH + j] : 0.0f;
    }
    for (int g = tid; g < GG; g += NTHR)
        wbsh[g] = make_float2(W_ih[g], b_ih[g] + b_hh[g]);
    for (int i = tid; i < 52; i += NTHR)
        wlin[i] = (i < HH) ? W_lin[i] : 0.0f;
    for (int i = tid; i < 64 * 64; i += NTHR)
        ((float*)hsw)[i] = 0.0f;     // covers full 16KB region (64*256B)

    const int bbase = blockIdx.x * BPB;
    const float* __restrict__ xg = x + (size_t)bbase * TT;

    // cell state for owned (j, batch) elements
    float cst[JPW][2];
#pragma unroll
    for (int a = 0; a < JPW; ++a) { cst[a][0] = 0.0f; cst[a][1] = 0.0f; }

    const int b0 = 2 * l;
    const int jbase = w * JPW;

    __syncthreads();

    for (int t = 0; t < TT; ++t) {
        // ---- refill x tile every 64 steps ----
        if ((t & 63) == 0) {
            for (int idx = tid; idx < 64 * 64; idx += NTHR) {
                int ttl = idx & 63, b = idx >> 6;
                xt[ttl * XROW + b] = xg[(size_t)b * TT + t + ttl];
            }
            __syncthreads();
        }

        // ---- load full h (both batches of this lane) into registers ----
        ull h2[2][26];
#pragma unroll
        for (int k = 0; k < 13; ++k) {
            ulonglong2 v0 = *(const ulonglong2*)(hsw + h_unit_off(b0, k));
            ulonglong2 v1 = *(const ulonglong2*)(hsw + h_unit_off(b0 + 1, k));
            h2[0][2 * k] = v0.x;  h2[0][2 * k + 1] = v0.y;
            h2[1][2 * k] = v1.x;  h2[1][2 * k + 1] = v1.y;
        }
        const float2 xv = *(const float2*)&xt[(t & 63) * XROW + b0];

#pragma unroll
        for (int jj = 0; jj < JPW; ++jj) {
            const int j = jbase + jj;
            float zb[4][2];
#pragma unroll
            for (int q = 0; q < 4; ++q) {
                const int g = q * HH + j;
                const float2 wb = wbsh[g];
                // acc packs (even-j partial, odd-j partial) per batch; 2 chains/batch
                ull a00 = pack2(fmaf(wb.x, xv.x, wb.y), 0.0f);
                ull a01 = 0ull;
                ull a10 = pack2(fmaf(wb.x, xv.y, wb.y), 0.0f);
                ull a11 = 0ull;
                const ulonglong2* __restrict__ wr =
                    (const ulonglong2*)(wsh + g * 52);
#pragma unroll
                for (int k = 0; k < 13; ++k) {
                    const ulonglong2 wv = wr[k];   // 4 weights, one broadcast LDS.128
                    a00 = ffma2(wv.x, h2[0][2 * k],     a00);
                    a01 = ffma2(wv.y, h2[0][2 * k + 1], a01);
                    a10 = ffma2(wv.x, h2[1][2 * k],     a10);
                    a11 = ffma2(wv.y, h2[1][2 * k + 1], a11);
                }
                ull s0 = fadd2(a00, a01);
                ull s1 = fadd2(a10, a11);
                float e0, o0, e1, o1;
                unpack2(s0, e0, o0);
                unpack2(s1, e1, o1);
                zb[q][0] = e0 + o0;
                zb[q][1] = e1 + o1;
            }
            // ---- activations + state update for (j, both batches) ----
#pragma unroll
            for (int bb = 0; bb < 2; ++bb) {
                const float iv = sigm(zb[0][bb]);
                const float fv = sigm(zb[1][bb]);
                const float gv = tanh_r(zb[2][bb]);
                const float ov = sigm(zb[3][bb]);
                const float c  = fmaf(fv, cst[jj][bb], iv * gv);
                cst[jj][bb] = c;
                const float hv = ov * tanh_r(c);
                *(float*)(hsw + h_elem_off(b0 + bb, j)) = hv;
            }
        }
        __syncthreads();
    }

    // ---- final projection (warp 0) ----
    if (w == 0) {
        const float bl = b_lin[0];
#pragma unroll
        for (int bb = 0; bb < 2; ++bb) {
            const int b = b0 + bb;
            float s = bl;
            for (int j = 0; j < HH; ++j)
                s = fmaf(wlin[j], *(const float*)(hsw + h_elem_off(b, j)), s);
            out[bbase + b] = s;
        }
    }
}

extern "C" void kernel_launch(void* const* d_in, const int* in_sizes, int n_in,
                              void* d_out, int out_size)
{
    const float* x     = (const float*)d_in[0];
    const float* W_ih  = (const float*)d_in[1];
    const float* W_hh  = (const float*)d_in[2];
    const float* b_ih  = (const float*)d_in[3];
    const float* b_hh  = (const float*)d_in[4];
    const float* W_lin = (const float*)d_in[5];
    const float* b_lin = (const float*)d_in[6];
    float* out = (float*)d_out;

    cudaFuncSetAttribute(lstm_persist_kernel,
                         cudaFuncAttributeMaxDynamicSharedMemorySize, SMEM_BYTES);

    lstm_persist_kernel<<<BB / BPB, NTHR, SMEM_BYTES>>>(
        x, W_ih, W_hh, b_ih, b_hh, W_lin, b_lin, out);
}